// round 10
// baseline (speedup 1.0000x reference)
#include <cuda_runtime.h>
#include <cuda_bf16.h>
#include <math.h>

// Problem constants
#define N_Q   32768
#define M_R   16384
#define KNN   8

// Spatial grid: 32^3 cells of size 3.0 covering [-48, 48]^3 (4.8 sigma).
// Out-of-range points clamp into edge cells (safe: clamping only moves a
// point's CELL inward, and edge cells make the termination bound infinite
// on that side).
#define GD        32
#define CELLS     (GD * GD * GD)        // 32768
#define HCELL     3.0f
#define INV_HCELL (1.0f / 3.0f)
#define HWORLD    48.0f

#define FULLMASK  0xffffffffu
#define INF_F     __int_as_float(0x7f800000)

// Scan geometry: 64 blocks of 512 elements per array (R, Q)
#define SCAN_BLKS   64
#define SCAN_ELEMS  512

// ---- device scratch (allocation-free rule) ----
__device__ int    g_cntR[CELLS], g_startR[CELLS], g_curR[CELLS];
__device__ int    g_cntQ[CELLS], g_startQ[CELLS], g_curQ[CELLS];
__device__ int    g_blk[2 * SCAN_BLKS];   // block totals (R then Q)
__device__ int    g_off[2 * SCAN_BLKS];   // exclusive block offsets
__device__ float4 g_refS[M_R];   // sorted refs: (-2x, -2y, -2z, |r|^2)
__device__ int    g_refId[M_R];  // sorted pos -> ORIGINAL ref index
__device__ float4 g_qS[N_Q];     // sorted queries: (x, y, z, |q|^2)
__device__ int    g_qId[N_Q];    // sorted pos -> original query index

__device__ __forceinline__ int clampi(int v, int lo, int hi) {
    return v < lo ? lo : (v > hi ? hi : v);
}

__device__ __forceinline__ void cellCoords(float x, float y, float z,
                                           int& cx, int& cy, int& cz) {
    cx = clampi((int)floorf((x + HWORLD) * INV_HCELL), 0, GD - 1);
    cy = clampi((int)floorf((y + HWORLD) * INV_HCELL), 0, GD - 1);
    cz = clampi((int)floorf((z + HWORLD) * INV_HCELL), 0, GD - 1);
}

__device__ __forceinline__ int flatCell(int cx, int cy, int cz) {
    return (cz * GD + cy) * GD + cx;
}

// ---------------------------------------------------------------------------
__global__ void zero_kernel() {
    int i = blockIdx.x * blockDim.x + threadIdx.x;
    if (i < CELLS)           g_cntR[i] = 0;
    else if (i < 2 * CELLS)  g_cntQ[i - CELLS] = 0;
}

__global__ void count_all(const float* __restrict__ ref,
                          const float* __restrict__ q) {
    int i = blockIdx.x * blockDim.x + threadIdx.x;
    if (i < M_R) {
        int cx, cy, cz;
        cellCoords(ref[3 * i], ref[3 * i + 1], ref[3 * i + 2], cx, cy, cz);
        atomicAdd(&g_cntR[flatCell(cx, cy, cz)], 1);
    } else if (i < M_R + N_Q) {
        int j = i - M_R;
        int cx, cy, cz;
        cellCoords(q[3 * j], q[3 * j + 1], q[3 * j + 2], cx, cy, cz);
        atomicAdd(&g_cntQ[flatCell(cx, cy, cz)], 1);
    }
}

// ---------------------------------------------------------------------------
// Coalesced 3-phase exclusive scan over the two 32768-entry count arrays.
// ---------------------------------------------------------------------------
__global__ __launch_bounds__(SCAN_ELEMS) void scan1_kernel() {
    const bool isQ = blockIdx.x >= SCAN_BLKS;
    const int  seg = isQ ? (blockIdx.x - SCAN_BLKS) : blockIdx.x;
    const int* cnt   = isQ ? g_cntQ   : g_cntR;
    int*       start = isQ ? g_startQ : g_startR;

    const int tid  = threadIdx.x;
    const int lane = tid & 31;
    const int wid  = tid >> 5;
    const int g    = seg * SCAN_ELEMS + tid;

    int v = cnt[g];          // coalesced
    int x = v;
#pragma unroll
    for (int o = 1; o < 32; o <<= 1) {
        int n = __shfl_up_sync(FULLMASK, x, o);
        if (lane >= o) x += n;
    }

    __shared__ int sw[16];
    if (lane == 31) sw[wid] = x;
    __syncthreads();
    if (wid == 0) {
        int y = (lane < 16) ? sw[lane] : 0;
#pragma unroll
        for (int o = 1; o < 16; o <<= 1) {
            int n = __shfl_up_sync(FULLMASK, y, o);
            if (lane >= o) y += n;
        }
        if (lane < 16) sw[lane] = y;   // inclusive warp totals
    }
    __syncthreads();

    int base = wid ? sw[wid - 1] : 0;
    int excl = base + x - v;
    start[g] = excl;                   // pre-offset; fixed in phase 3
    if (tid == SCAN_ELEMS - 1) g_blk[blockIdx.x] = excl + v;
}

__global__ void scan2_kernel() {
    int lane = threadIdx.x;
#pragma unroll
    for (int half = 0; half < 2; ++half) {
        int base = half * SCAN_BLKS;
        int a = g_blk[base + 2 * lane];
        int b = g_blk[base + 2 * lane + 1];
        int s = a + b;
        int x = s;
#pragma unroll
        for (int o = 1; o < 32; o <<= 1) {
            int n = __shfl_up_sync(FULLMASK, x, o);
            if (lane >= o) x += n;
        }
        int exclPair = x - s;
        g_off[base + 2 * lane]     = exclPair;
        g_off[base + 2 * lane + 1] = exclPair + a;
    }
}

__global__ __launch_bounds__(SCAN_ELEMS) void scan3_kernel() {
    const bool isQ = blockIdx.x >= SCAN_BLKS;
    const int  seg = isQ ? (blockIdx.x - SCAN_BLKS) : blockIdx.x;
    int* start = isQ ? g_startQ : g_startR;
    int* cur   = isQ ? g_curQ   : g_curR;

    int g = seg * SCAN_ELEMS + threadIdx.x;
    int v = start[g] + g_off[blockIdx.x];
    start[g] = v;
    cur[g]   = v;
}

// ---------------------------------------------------------------------------
__global__ void scatter_all(const float* __restrict__ ref,
                            const float* __restrict__ q) {
    int i = blockIdx.x * blockDim.x + threadIdx.x;
    if (i < M_R) {
        float x = ref[3 * i], y = ref[3 * i + 1], z = ref[3 * i + 2];
        int cx, cy, cz;
        cellCoords(x, y, z, cx, cy, cz);
        int p = atomicAdd(&g_curR[flatCell(cx, cy, cz)], 1);
        g_refS[p]  = make_float4(-2.0f * x, -2.0f * y, -2.0f * z,
                                 x * x + y * y + z * z);
        g_refId[p] = i;
    } else if (i < M_R + N_Q) {
        int j = i - M_R;
        float x = q[3 * j], y = q[3 * j + 1], z = q[3 * j + 2];
        int cx, cy, cz;
        cellCoords(x, y, z, cx, cy, cz);
        int p = atomicAdd(&g_curQ[flatCell(cx, cy, cz)], 1);
        g_qS[p]  = make_float4(x, y, z, x * x + y * y + z * z);
        g_qId[p] = j;
    }
}

// ---------------------------------------------------------------------------
// Tuple-ordered 8-best insertion: total order is (d', originalId) lex.
// Caller guarantees (d,oid) < (b[7],boid[7]). This makes the kept set EXACTLY
// the 8 smallest by (d', origId) — identical to the brute-force/reference
// semantics (jax top_k keeps the lowest index among ties) — independent of
// scan order, lane partition, and scatter nondeterminism.
// ---------------------------------------------------------------------------
__device__ __forceinline__ void insert8(float d, int oid,
                                        float (&b)[KNN], int (&boid)[KNN]) {
    b[7] = d; boid[7] = oid;
#pragma unroll
    for (int k = 7; k > 0; --k) {
        bool sw = (b[k] < b[k - 1]) || (b[k] == b[k - 1] && boid[k] < boid[k - 1]);
        if (sw) {
            float t = b[k];   b[k] = b[k - 1];     b[k - 1] = t;
            int   u = boid[k]; boid[k] = boid[k - 1]; boid[k - 1] = u;
        }
    }
}

// ---------------------------------------------------------------------------
// Warp-per-query KNN: 32 lanes cooperate on ONE query (warp-uniform control
// flow). Lanes stride over points within each cell, keep per-lane top-8 by
// (d', origId), then merge via 8 warp argmin-pops on the same tuple order.
// d' = |r|^2 - 2 q.r ; true d^2 = d' + |q|^2 (per-query constant).
// ---------------------------------------------------------------------------
#define WPB 8   // warps per block
__global__ __launch_bounds__(WPB * 32) void knn_kernel(const float* __restrict__ flow,
                                                       float* __restrict__ out) {
    const int t    = blockIdx.x * WPB + (threadIdx.x >> 5);  // query slot
    const int lane = threadIdx.x & 31;

    const float4 qp = g_qS[t];
    const float qx = qp.x, qy = qp.y, qz = qp.z, q2 = qp.w;

    int cx, cy, cz;
    cellCoords(qx, qy, qz, cx, cy, cz);

    float b[KNN];
    int   boid[KNN];
#pragma unroll
    for (int k = 0; k < KNN; ++k) { b[k] = INF_F; boid[k] = 0x7fffffff; }

    for (int s = 0; s < GD; ++s) {
        int x0 = max(cx - s, 0), x1 = min(cx + s, GD - 1);
        int y0 = max(cy - s, 0), y1 = min(cy + s, GD - 1);
        int z0 = max(cz - s, 0), z1 = min(cz + s, GD - 1);

        for (int zz = z0; zz <= z1; ++zz) {
            int dz = abs(zz - cz);
            for (int yy = y0; yy <= y1; ++yy) {
                int dyz = max(abs(yy - cy), dz);
                for (int xx = x0; xx <= x1; ++xx) {
                    if (max(abs(xx - cx), dyz) != s) continue;   // ring only
                    int c   = flatCell(xx, yy, zz);
                    int beg = g_startR[c];   // uniform addr: broadcast loads
                    int cnt = g_cntR[c];
                    for (int j0 = 0; j0 < cnt; j0 += 32) {
                        int j = j0 + lane;
                        if (j < cnt) {
                            float4 r = g_refS[beg + j];
                            float d = fmaf(r.x, qx,
                                      fmaf(r.y, qy, fmaf(r.z, qz, r.w)));
                            if (d <= b[7]) {             // hot-path: 1 setp
                                int oid = g_refId[beg + j];   // rare path
                                if (d < b[7] || oid < boid[7])
                                    insert8(d, oid, b, boid);
                            }
                        }
                    }
                }
            }
        }

        bool full = (x0 == 0) && (y0 == 0) && (z0 == 0) &&
                    (x1 == GD - 1) && (y1 == GD - 1) && (z1 == GD - 1);
        if (full) break;

        // Conservative global-d8 upper bound: min over lanes of local b[7]
        // (each lane's 8 kept values are all <= its b[7]).
        float ub = b[7];
#pragma unroll
        for (int o = 16; o; o >>= 1)
            ub = fminf(ub, __shfl_xor_sync(FULLMASK, ub, o));

        // Distance from query to visited-box boundary (edge-clipped sides
        // extend to infinity: clamped points live in edge cells).
        float lox = (x0 == 0)      ? -1e30f : (x0 * HCELL - HWORLD);
        float hix = (x1 == GD - 1) ?  1e30f : ((x1 + 1) * HCELL - HWORLD);
        float loy = (y0 == 0)      ? -1e30f : (y0 * HCELL - HWORLD);
        float hiy = (y1 == GD - 1) ?  1e30f : ((y1 + 1) * HCELL - HWORLD);
        float loz = (z0 == 0)      ? -1e30f : (z0 * HCELL - HWORLD);
        float hiz = (z1 == GD - 1) ?  1e30f : ((z1 + 1) * HCELL - HWORLD);

        float m = fminf(qx - lox, hix - qx);
        m = fminf(m, fminf(qy - loy, hiy - qy));
        m = fminf(m, fminf(qz - loz, hiz - qz));

        // STRICT > : an unexamined point at distance exactly d8 could still
        // win the (d, origId) tie-break, so only stop when strictly farther.
        if (ub < 1e30f && m > 0.0f) {
            float d8sq = fmaxf(ub + q2, 0.0f);
            if (m * m > d8sq) break;
        }
    }

    // ---- merge: pop the 8 globally smallest by (val, origId); lane r keeps
    // the r-th neighbor so the flow gather runs in parallel on lanes 0..7.
    float selD = 0.0f;
    int   selI = 0;
#pragma unroll
    for (int r = 0; r < KNN; ++r) {
        float bv = b[0];
        int   bo = boid[0];
        int   bl = lane;
#pragma unroll
        for (int o = 16; o; o >>= 1) {
            float ov = __shfl_xor_sync(FULLMASK, bv, o);
            int   oo = __shfl_xor_sync(FULLMASK, bo, o);
            int   ol = __shfl_xor_sync(FULLMASK, bl, o);
            if (ov < bv || (ov == bv && oo < bo)) { bv = ov; bo = oo; bl = ol; }
        }
        if (lane == r) { selD = bv; selI = bo; }
        if (lane == bl) {   // pop winner's head
#pragma unroll
            for (int k = 0; k < KNN - 1; ++k) { b[k] = b[k + 1]; boid[k] = boid[k + 1]; }
            b[KNN - 1] = INF_F; boid[KNN - 1] = 0x7fffffff;
        }
    }

    // IDW: POWER=2 -> w = 1/(d^2 + eps); no sqrt.
    float w = 0.0f, fx = 0.0f, fy = 0.0f, fz = 0.0f;
    if (lane < KNN) {
        float d2 = fmaxf(selD + q2, 0.0f);
        w = 1.0f / (d2 + 1e-8f);
        fx = w * flow[3 * selI + 0];
        fy = w * flow[3 * selI + 1];
        fz = w * flow[3 * selI + 2];
    }
#pragma unroll
    for (int o = 16; o; o >>= 1) {
        w  += __shfl_xor_sync(FULLMASK, w,  o);
        fx += __shfl_xor_sync(FULLMASK, fx, o);
        fy += __shfl_xor_sync(FULLMASK, fy, o);
        fz += __shfl_xor_sync(FULLMASK, fz, o);
    }

    if (lane == 0) {
        float inv = 1.0f / w;
        int qo = g_qId[t];
        out[3 * qo + 0] = fx * inv;
        out[3 * qo + 1] = fy * inv;
        out[3 * qo + 2] = fz * inv;
    }
}

// ---------------------------------------------------------------------------
extern "C" void kernel_launch(void* const* d_in, const int* in_sizes, int n_in,
                              void* d_out, int out_size) {
    const float* q   = (const float*)d_in[0];  // query_points [N,3]
    const float* r   = (const float*)d_in[1];  // ref_points   [M,3]
    const float* f   = (const float*)d_in[2];  // ref_flow     [M,3]
    float*       out = (float*)d_out;          // [N,3]

    zero_kernel<<<(2 * CELLS + 255) / 256, 256>>>();
    count_all<<<(M_R + N_Q + 255) / 256, 256>>>(r, q);
    scan1_kernel<<<2 * SCAN_BLKS, SCAN_ELEMS>>>();
    scan2_kernel<<<1, 32>>>();
    scan3_kernel<<<2 * SCAN_BLKS, SCAN_ELEMS>>>();
    scatter_all<<<(M_R + N_Q + 255) / 256, 256>>>(r, q);
    knn_kernel<<<N_Q / WPB, WPB * 32>>>(f, out);
}

// round 12
// speedup vs baseline: 1.5251x; 1.5251x over previous
#include <cuda_runtime.h>
#include <cuda_bf16.h>
#include <math.h>

// Problem constants
#define N_Q   32768
#define M_R   16384
#define KNN   8

// Spatial grid: 32^3 cells of size 3.0 covering [-48, 48]^3.
// Out-of-range points clamp into edge cells (clamping only moves a point's
// CELL inward; edge-clipped sides of a visited box are exhaustive, so the
// termination bound is infinite on those sides).
#define GD        32
#define CELLS     (GD * GD * GD)        // 32768
#define HCELL     3.0f
#define INV_HCELL (1.0f / 3.0f)
#define HWORLD    48.0f

#define FULLMASK  0xffffffffu
#define INF_F     __int_as_float(0x7f800000)

// Scan geometry: 64 blocks of 512 elements per array (R, Q)
#define SCAN_BLKS   64
#define SCAN_ELEMS  512

// ---- device scratch (allocation-free rule) ----
__device__ int    g_cntR[CELLS], g_startR[CELLS], g_curR[CELLS];
__device__ int    g_cntQ[CELLS], g_startQ[CELLS], g_curQ[CELLS];
__device__ int    g_blk[2 * SCAN_BLKS];
__device__ int    g_off[2 * SCAN_BLKS];
__device__ float4 g_refS[M_R];   // sorted refs: (-2x, -2y, -2z, |r|^2)
__device__ int    g_refId[M_R];  // sorted pos -> ORIGINAL ref index
__device__ float4 g_qS[N_Q];     // sorted queries: (x, y, z, |q|^2)
__device__ int    g_qId[N_Q];    // sorted pos -> original query index
__device__ int    g_fb[N_Q];     // fallback query slots
__device__ int    g_fbCnt;

__device__ __forceinline__ int clampi(int v, int lo, int hi) {
    return v < lo ? lo : (v > hi ? hi : v);
}

__device__ __forceinline__ void cellCoords(float x, float y, float z,
                                           int& cx, int& cy, int& cz) {
    cx = clampi((int)floorf((x + HWORLD) * INV_HCELL), 0, GD - 1);
    cy = clampi((int)floorf((y + HWORLD) * INV_HCELL), 0, GD - 1);
    cz = clampi((int)floorf((z + HWORLD) * INV_HCELL), 0, GD - 1);
}

__device__ __forceinline__ int flatCell(int cx, int cy, int cz) {
    return (cz * GD + cy) * GD + cx;
}

// ---------------------------------------------------------------------------
__global__ void zero_kernel() {
    int i = blockIdx.x * blockDim.x + threadIdx.x;
    if (i == 0)              g_fbCnt = 0;
    if (i < CELLS)           g_cntR[i] = 0;
    else if (i < 2 * CELLS)  g_cntQ[i - CELLS] = 0;
}

__global__ void count_all(const float* __restrict__ ref,
                          const float* __restrict__ q) {
    int i = blockIdx.x * blockDim.x + threadIdx.x;
    if (i < M_R) {
        int cx, cy, cz;
        cellCoords(ref[3 * i], ref[3 * i + 1], ref[3 * i + 2], cx, cy, cz);
        atomicAdd(&g_cntR[flatCell(cx, cy, cz)], 1);
    } else if (i < M_R + N_Q) {
        int j = i - M_R;
        int cx, cy, cz;
        cellCoords(q[3 * j], q[3 * j + 1], q[3 * j + 2], cx, cy, cz);
        atomicAdd(&g_cntQ[flatCell(cx, cy, cz)], 1);
    }
}

// ---------------------------------------------------------------------------
// Coalesced 3-phase exclusive scan over the two 32768-entry count arrays.
// ---------------------------------------------------------------------------
__global__ __launch_bounds__(SCAN_ELEMS) void scan1_kernel() {
    const bool isQ = blockIdx.x >= SCAN_BLKS;
    const int  seg = isQ ? (blockIdx.x - SCAN_BLKS) : blockIdx.x;
    const int* cnt   = isQ ? g_cntQ   : g_cntR;
    int*       start = isQ ? g_startQ : g_startR;

    const int tid  = threadIdx.x;
    const int lane = tid & 31;
    const int wid  = tid >> 5;
    const int g    = seg * SCAN_ELEMS + tid;

    int v = cnt[g];
    int x = v;
#pragma unroll
    for (int o = 1; o < 32; o <<= 1) {
        int n = __shfl_up_sync(FULLMASK, x, o);
        if (lane >= o) x += n;
    }

    __shared__ int sw[16];
    if (lane == 31) sw[wid] = x;
    __syncthreads();
    if (wid == 0) {
        int y = (lane < 16) ? sw[lane] : 0;
#pragma unroll
        for (int o = 1; o < 16; o <<= 1) {
            int n = __shfl_up_sync(FULLMASK, y, o);
            if (lane >= o) y += n;
        }
        if (lane < 16) sw[lane] = y;
    }
    __syncthreads();

    int base = wid ? sw[wid - 1] : 0;
    int excl = base + x - v;
    start[g] = excl;
    if (tid == SCAN_ELEMS - 1) g_blk[blockIdx.x] = excl + v;
}

__global__ void scan2_kernel() {
    int lane = threadIdx.x;
#pragma unroll
    for (int half = 0; half < 2; ++half) {
        int base = half * SCAN_BLKS;
        int a = g_blk[base + 2 * lane];
        int b = g_blk[base + 2 * lane + 1];
        int s = a + b;
        int x = s;
#pragma unroll
        for (int o = 1; o < 32; o <<= 1) {
            int n = __shfl_up_sync(FULLMASK, x, o);
            if (lane >= o) x += n;
        }
        int exclPair = x - s;
        g_off[base + 2 * lane]     = exclPair;
        g_off[base + 2 * lane + 1] = exclPair + a;
    }
}

__global__ __launch_bounds__(SCAN_ELEMS) void scan3_kernel() {
    const bool isQ = blockIdx.x >= SCAN_BLKS;
    const int  seg = isQ ? (blockIdx.x - SCAN_BLKS) : blockIdx.x;
    int* start = isQ ? g_startQ : g_startR;
    int* cur   = isQ ? g_curQ   : g_curR;

    int g = seg * SCAN_ELEMS + threadIdx.x;
    int v = start[g] + g_off[blockIdx.x];
    start[g] = v;
    cur[g]   = v;
}

// ---------------------------------------------------------------------------
__global__ void scatter_all(const float* __restrict__ ref,
                            const float* __restrict__ q) {
    int i = blockIdx.x * blockDim.x + threadIdx.x;
    if (i < M_R) {
        float x = ref[3 * i], y = ref[3 * i + 1], z = ref[3 * i + 2];
        int cx, cy, cz;
        cellCoords(x, y, z, cx, cy, cz);
        int p = atomicAdd(&g_curR[flatCell(cx, cy, cz)], 1);
        g_refS[p]  = make_float4(-2.0f * x, -2.0f * y, -2.0f * z,
                                 x * x + y * y + z * z);
        g_refId[p] = i;
    } else if (i < M_R + N_Q) {
        int j = i - M_R;
        float x = q[3 * j], y = q[3 * j + 1], z = q[3 * j + 2];
        int cx, cy, cz;
        cellCoords(x, y, z, cx, cy, cz);
        int p = atomicAdd(&g_curQ[flatCell(cx, cy, cz)], 1);
        g_qS[p]  = make_float4(x, y, z, x * x + y * y + z * z);
        g_qId[p] = j;
    }
}

// ---------------------------------------------------------------------------
// Tuple-ordered 8-best insertion: total order is (d', originalId) lex.
// Caller guarantees (d,oid) < (b[7],boid[7]). Keeps EXACTLY the 8 smallest by
// (d', origId) — identical to the brute-force/reference semantics — for any
// candidate arrival order. (Verified in round 10: rel_err matches brute force.)
// ---------------------------------------------------------------------------
__device__ __forceinline__ void insert8(float d, int oid,
                                        float (&b)[KNN], int (&boid)[KNN]) {
    b[7] = d; boid[7] = oid;
#pragma unroll
    for (int k = 7; k > 0; --k) {
        bool sw = (b[k] < b[k - 1]) || (b[k] == b[k - 1] && boid[k] < boid[k - 1]);
        if (sw) {
            float t = b[k];   b[k] = b[k - 1];     b[k - 1] = t;
            int   u = boid[k]; boid[k] = boid[k - 1]; boid[k - 1] = u;
        }
    }
}

// ---------------------------------------------------------------------------
// PASS A: thread-per-query over the fixed 3x3x3 cell neighborhood.
// x-adjacent cells are contiguous in the sorted ref array, so each (zz,yy)
// row of up to 3 cells is ONE contiguous range: 9 range loops, warp-uniform.
// Valid iff the 8th-best distance is STRICTLY inside the box bound m
// (edge-clipped sides contribute +inf). Invalid queries go to the fallback
// list for pass B.
// ---------------------------------------------------------------------------
__global__ __launch_bounds__(128) void knnA_kernel(const float* __restrict__ flow,
                                                   float* __restrict__ out) {
    const int t = blockIdx.x * 128 + threadIdx.x;
    const float4 qp = g_qS[t];
    const float qx = qp.x, qy = qp.y, qz = qp.z, q2 = qp.w;

    int cx, cy, cz;
    cellCoords(qx, qy, qz, cx, cy, cz);
    const int x0 = max(cx - 1, 0), x1 = min(cx + 1, GD - 1);
    const int y0 = max(cy - 1, 0), y1 = min(cy + 1, GD - 1);
    const int z0 = max(cz - 1, 0), z1 = min(cz + 1, GD - 1);

    float b[KNN];
    int   boid[KNN];
#pragma unroll
    for (int k = 0; k < KNN; ++k) { b[k] = INF_F; boid[k] = 0x7fffffff; }

    for (int zz = z0; zz <= z1; ++zz) {
        for (int yy = y0; yy <= y1; ++yy) {
            int cLo = flatCell(x0, yy, zz);
            int cHi = flatCell(x1, yy, zz);
            int j   = g_startR[cLo];
            int end = g_startR[cHi] + g_cntR[cHi];
            for (; j < end; ++j) {
                float4 r = g_refS[j];
                float d = fmaf(r.x, qx, fmaf(r.y, qy, fmaf(r.z, qz, r.w)));
                if (d <= b[7]) {                        // hot path: 1 setp
                    int oid = g_refId[j];               // rare path
                    if (d < b[7] || oid < boid[7])
                        insert8(d, oid, b, boid);
                }
            }
        }
    }

    // Exact distance from query to the visited 3x3x3 box boundary.
    float lox = (x0 == 0)      ? -1e30f : (x0 * HCELL - HWORLD);
    float hix = (x1 == GD - 1) ?  1e30f : ((x1 + 1) * HCELL - HWORLD);
    float loy = (y0 == 0)      ? -1e30f : (y0 * HCELL - HWORLD);
    float hiy = (y1 == GD - 1) ?  1e30f : ((y1 + 1) * HCELL - HWORLD);
    float loz = (z0 == 0)      ? -1e30f : (z0 * HCELL - HWORLD);
    float hiz = (z1 == GD - 1) ?  1e30f : ((z1 + 1) * HCELL - HWORLD);

    float m = fminf(qx - lox, hix - qx);
    m = fminf(m, fminf(qy - loy, hiy - qy));
    m = fminf(m, fminf(qz - loz, hiz - qz));

    float d8sq = fmaxf(b[7] + q2, 0.0f);   // inf if list not full
    // STRICT <: a point exactly at distance m could win the origId tie-break.
    bool valid = (b[7] < 1e30f) && (m > 0.0f) && (d8sq < m * m);

    if (!valid) {
        int p = atomicAdd(&g_fbCnt, 1);
        g_fb[p] = t;
        return;
    }

    // IDW: POWER=2 -> w = 1/(d^2 + eps); no sqrt.
    float wsum = 0.0f, ax = 0.0f, ay = 0.0f, az = 0.0f;
#pragma unroll
    for (int k = 0; k < KNN; ++k) {
        float d2 = fmaxf(b[k] + q2, 0.0f);
        float w  = 1.0f / (d2 + 1e-8f);
        int  id  = boid[k];
        wsum += w;
        ax = fmaf(w, flow[3 * id + 0], ax);
        ay = fmaf(w, flow[3 * id + 1], ay);
        az = fmaf(w, flow[3 * id + 2], az);
    }
    float inv = 1.0f / wsum;
    int qo = g_qId[t];
    out[3 * qo + 0] = ax * inv;
    out[3 * qo + 1] = ay * inv;
    out[3 * qo + 2] = az * inv;
}

// ---------------------------------------------------------------------------
// PASS B: warp-per-query brute force over ALL refs for fallback queries.
// GRID-STRIDE over the fallback list (round-11 bug: fixed 1024 warp slots
// silently dropped fallbacks beyond capacity -> poisoned outputs).
// Lanes stride refs (coalesced float4 loads), per-lane top-8 by (d', origId),
// warp merge via 8 argmin pops on the same tuple order (verified correct).
// ---------------------------------------------------------------------------
#define BWPB     8
#define B_BLOCKS 256    // 2048 warps; each handles ceil(fbCnt/2048) queries
__global__ __launch_bounds__(BWPB * 32) void knnB_kernel(const float* __restrict__ flow,
                                                         float* __restrict__ out) {
    const int warpG  = blockIdx.x * BWPB + (threadIdx.x >> 5);
    const int nWarps = gridDim.x * BWPB;
    const int lane   = threadIdx.x & 31;
    const int fbCnt  = g_fbCnt;

    for (int w = warpG; w < fbCnt; w += nWarps) {
        const int t = g_fb[w];

        const float4 qp = g_qS[t];
        const float qx = qp.x, qy = qp.y, qz = qp.z, q2 = qp.w;

        float b[KNN];
        int   boid[KNN];
#pragma unroll
        for (int k = 0; k < KNN; ++k) { b[k] = INF_F; boid[k] = 0x7fffffff; }

        for (int j = lane; j < M_R; j += 32) {   // coalesced across lanes
            float4 r = g_refS[j];
            float d = fmaf(r.x, qx, fmaf(r.y, qy, fmaf(r.z, qz, r.w)));
            if (d <= b[7]) {
                int oid = g_refId[j];
                if (d < b[7] || oid < boid[7])
                    insert8(d, oid, b, boid);
            }
        }

        // Merge: pop the 8 globally smallest by (val, origId); lane r keeps
        // the r-th neighbor so the flow gather runs on lanes 0..7.
        float selD = 0.0f;
        int   selI = 0;
#pragma unroll
        for (int r = 0; r < KNN; ++r) {
            float bv = b[0];
            int   bo = boid[0];
            int   bl = lane;
#pragma unroll
            for (int o = 16; o; o >>= 1) {
                float ov = __shfl_xor_sync(FULLMASK, bv, o);
                int   oo = __shfl_xor_sync(FULLMASK, bo, o);
                int   ol = __shfl_xor_sync(FULLMASK, bl, o);
                if (ov < bv || (ov == bv && oo < bo)) { bv = ov; bo = oo; bl = ol; }
            }
            if (lane == r) { selD = bv; selI = bo; }
            if (lane == bl) {
#pragma unroll
                for (int k = 0; k < KNN - 1; ++k) { b[k] = b[k + 1]; boid[k] = boid[k + 1]; }
                b[KNN - 1] = INF_F; boid[KNN - 1] = 0x7fffffff;
            }
        }

        float ww = 0.0f, fx = 0.0f, fy = 0.0f, fz = 0.0f;
        if (lane < KNN) {
            float d2 = fmaxf(selD + q2, 0.0f);
            ww = 1.0f / (d2 + 1e-8f);
            fx = ww * flow[3 * selI + 0];
            fy = ww * flow[3 * selI + 1];
            fz = ww * flow[3 * selI + 2];
        }
#pragma unroll
        for (int o = 16; o; o >>= 1) {
            ww += __shfl_xor_sync(FULLMASK, ww, o);
            fx += __shfl_xor_sync(FULLMASK, fx, o);
            fy += __shfl_xor_sync(FULLMASK, fy, o);
            fz += __shfl_xor_sync(FULLMASK, fz, o);
        }

        if (lane == 0) {
            float inv = 1.0f / ww;
            int qo = g_qId[t];
            out[3 * qo + 0] = fx * inv;
            out[3 * qo + 1] = fy * inv;
            out[3 * qo + 2] = fz * inv;
        }
    }
}

// ---------------------------------------------------------------------------
extern "C" void kernel_launch(void* const* d_in, const int* in_sizes, int n_in,
                              void* d_out, int out_size) {
    const float* q   = (const float*)d_in[0];  // query_points [N,3]
    const float* r   = (const float*)d_in[1];  // ref_points   [M,3]
    const float* f   = (const float*)d_in[2];  // ref_flow     [M,3]
    float*       out = (float*)d_out;          // [N,3]

    zero_kernel<<<(2 * CELLS + 255) / 256, 256>>>();
    count_all<<<(M_R + N_Q + 255) / 256, 256>>>(r, q);
    scan1_kernel<<<2 * SCAN_BLKS, SCAN_ELEMS>>>();
    scan2_kernel<<<1, 32>>>();
    scan3_kernel<<<2 * SCAN_BLKS, SCAN_ELEMS>>>();
    scatter_all<<<(M_R + N_Q + 255) / 256, 256>>>(r, q);
    knnA_kernel<<<N_Q / 128, 128>>>(f, out);
    knnB_kernel<<<B_BLOCKS, BWPB * 32>>>(f, out);
}

// round 14
// speedup vs baseline: 1.7190x; 1.1271x over previous
#include <cuda_runtime.h>
#include <cuda_bf16.h>
#include <math.h>

// Problem constants
#define N_Q   32768
#define M_R   16384
#define KNN   8

// Spatial grid: 32^3 cells of size 3.0 covering [-48, 48]^3.
// Out-of-range points clamp into edge cells (clamping only moves a point's
// CELL inward; edge-clipped sides of a visited box are exhaustive, so the
// termination bound is infinite on those sides).
#define GD        32
#define CELLS     (GD * GD * GD)        // 32768
#define HCELL     3.0f
#define INV_HCELL (1.0f / 3.0f)
#define HWORLD    48.0f

#define FULLMASK  0xffffffffu
#define INF_F     __int_as_float(0x7f800000)

// Scan geometry: 64 blocks of 512 elements per array (R, Q)
#define SCAN_BLKS   64
#define SCAN_ELEMS  512

// ---- device scratch (allocation-free rule) ----
__device__ int    g_cntR[CELLS], g_startR[CELLS], g_curR[CELLS];
__device__ int    g_cntQ[CELLS], g_startQ[CELLS], g_curQ[CELLS];
__device__ int    g_blk[2 * SCAN_BLKS];
__device__ int    g_off[2 * SCAN_BLKS];
__device__ float4 g_refS[M_R];    // sorted refs: (-2x, -2y, -2z, |r|^2)
__device__ int    g_refId[M_R];   // sorted pos -> ORIGINAL ref index
__device__ float4 g_qS[N_Q];      // sorted queries: (x, y, z, |q|^2)
__device__ int    g_qId[N_Q];     // sorted pos -> original query index
__device__ int    g_fb[N_Q];      // fallback query slots
__device__ float  g_fbSeedD[N_Q]; // pass-A 8th-best d'  (upper bound on true d8)
__device__ int    g_fbSeedO[N_Q]; // pass-A 8th-best origId (tie-break part)
__device__ int    g_fbCnt;

__device__ __forceinline__ int clampi(int v, int lo, int hi) {
    return v < lo ? lo : (v > hi ? hi : v);
}

__device__ __forceinline__ void cellCoords(float x, float y, float z,
                                           int& cx, int& cy, int& cz) {
    cx = clampi((int)floorf((x + HWORLD) * INV_HCELL), 0, GD - 1);
    cy = clampi((int)floorf((y + HWORLD) * INV_HCELL), 0, GD - 1);
    cz = clampi((int)floorf((z + HWORLD) * INV_HCELL), 0, GD - 1);
}

__device__ __forceinline__ int flatCell(int cx, int cy, int cz) {
    return (cz * GD + cy) * GD + cx;
}

// ---------------------------------------------------------------------------
__global__ void zero_kernel() {
    int i = blockIdx.x * blockDim.x + threadIdx.x;
    if (i == 0)              g_fbCnt = 0;
    if (i < CELLS)           g_cntR[i] = 0;
    else if (i < 2 * CELLS)  g_cntQ[i - CELLS] = 0;
}

__global__ void count_all(const float* __restrict__ ref,
                          const float* __restrict__ q) {
    int i = blockIdx.x * blockDim.x + threadIdx.x;
    if (i < M_R) {
        int cx, cy, cz;
        cellCoords(ref[3 * i], ref[3 * i + 1], ref[3 * i + 2], cx, cy, cz);
        atomicAdd(&g_cntR[flatCell(cx, cy, cz)], 1);
    } else if (i < M_R + N_Q) {
        int j = i - M_R;
        int cx, cy, cz;
        cellCoords(q[3 * j], q[3 * j + 1], q[3 * j + 2], cx, cy, cz);
        atomicAdd(&g_cntQ[flatCell(cx, cy, cz)], 1);
    }
}

// ---------------------------------------------------------------------------
// Coalesced 3-phase exclusive scan over the two 32768-entry count arrays.
// ---------------------------------------------------------------------------
__global__ __launch_bounds__(SCAN_ELEMS) void scan1_kernel() {
    const bool isQ = blockIdx.x >= SCAN_BLKS;
    const int  seg = isQ ? (blockIdx.x - SCAN_BLKS) : blockIdx.x;
    const int* cnt   = isQ ? g_cntQ   : g_cntR;
    int*       start = isQ ? g_startQ : g_startR;

    const int tid  = threadIdx.x;
    const int lane = tid & 31;
    const int wid  = tid >> 5;
    const int g    = seg * SCAN_ELEMS + tid;

    int v = cnt[g];
    int x = v;
#pragma unroll
    for (int o = 1; o < 32; o <<= 1) {
        int n = __shfl_up_sync(FULLMASK, x, o);
        if (lane >= o) x += n;
    }

    __shared__ int sw[16];
    if (lane == 31) sw[wid] = x;
    __syncthreads();
    if (wid == 0) {
        int y = (lane < 16) ? sw[lane] : 0;
#pragma unroll
        for (int o = 1; o < 16; o <<= 1) {
            int n = __shfl_up_sync(FULLMASK, y, o);
            if (lane >= o) y += n;
        }
        if (lane < 16) sw[lane] = y;
    }
    __syncthreads();

    int base = wid ? sw[wid - 1] : 0;
    int excl = base + x - v;
    start[g] = excl;
    if (tid == SCAN_ELEMS - 1) g_blk[blockIdx.x] = excl + v;
}

__global__ void scan2_kernel() {
    int lane = threadIdx.x;
#pragma unroll
    for (int half = 0; half < 2; ++half) {
        int base = half * SCAN_BLKS;
        int a = g_blk[base + 2 * lane];
        int b = g_blk[base + 2 * lane + 1];
        int s = a + b;
        int x = s;
#pragma unroll
        for (int o = 1; o < 32; o <<= 1) {
            int n = __shfl_up_sync(FULLMASK, x, o);
            if (lane >= o) x += n;
        }
        int exclPair = x - s;
        g_off[base + 2 * lane]     = exclPair;
        g_off[base + 2 * lane + 1] = exclPair + a;
    }
}

__global__ __launch_bounds__(SCAN_ELEMS) void scan3_kernel() {
    const bool isQ = blockIdx.x >= SCAN_BLKS;
    const int  seg = isQ ? (blockIdx.x - SCAN_BLKS) : blockIdx.x;
    int* start = isQ ? g_startQ : g_startR;
    int* cur   = isQ ? g_curQ   : g_curR;

    int g = seg * SCAN_ELEMS + threadIdx.x;
    int v = start[g] + g_off[blockIdx.x];
    start[g] = v;
    cur[g]   = v;
}

// ---------------------------------------------------------------------------
__global__ void scatter_all(const float* __restrict__ ref,
                            const float* __restrict__ q) {
    int i = blockIdx.x * blockDim.x + threadIdx.x;
    if (i < M_R) {
        float x = ref[3 * i], y = ref[3 * i + 1], z = ref[3 * i + 2];
        int cx, cy, cz;
        cellCoords(x, y, z, cx, cy, cz);
        int p = atomicAdd(&g_curR[flatCell(cx, cy, cz)], 1);
        g_refS[p]  = make_float4(-2.0f * x, -2.0f * y, -2.0f * z,
                                 x * x + y * y + z * z);
        g_refId[p] = i;
    } else if (i < M_R + N_Q) {
        int j = i - M_R;
        float x = q[3 * j], y = q[3 * j + 1], z = q[3 * j + 2];
        int cx, cy, cz;
        cellCoords(x, y, z, cx, cy, cz);
        int p = atomicAdd(&g_curQ[flatCell(cx, cy, cz)], 1);
        g_qS[p]  = make_float4(x, y, z, x * x + y * y + z * z);
        g_qId[p] = j;
    }
}

// ---------------------------------------------------------------------------
// Tuple-ordered 8-best insertion: total order is (d', originalId) lex.
// Caller guarantees (d,oid) < (b[7],boid[7]). Keeps EXACTLY the 8 smallest by
// (d', origId) — identical to brute-force/reference semantics — for any
// candidate arrival order. (Verified: rel_err matches brute force.)
// ---------------------------------------------------------------------------
__device__ __forceinline__ void insert8(float d, int oid,
                                        float (&b)[KNN], int (&boid)[KNN]) {
    b[7] = d; boid[7] = oid;
#pragma unroll
    for (int k = 7; k > 0; --k) {
        bool sw = (b[k] < b[k - 1]) || (b[k] == b[k - 1] && boid[k] < boid[k - 1]);
        if (sw) {
            float t = b[k];   b[k] = b[k - 1];     b[k - 1] = t;
            int   u = boid[k]; boid[k] = boid[k - 1]; boid[k - 1] = u;
        }
    }
}

// ---------------------------------------------------------------------------
// PASS A: thread-per-query over the fixed 3x3x3 cell neighborhood.
// x-adjacent cells are contiguous in the sorted ref array, so each (zz,yy)
// row of up to 3 cells is ONE contiguous range: 9 range loops, warp-uniform.
// Valid iff the 8th-best distance is STRICTLY inside the box bound m.
// Invalid queries go to the fallback list WITH their 8th-best (d,oid) as a
// SEED: the true d8 key is provably <= this seed (it is the max of an
// 8-candidate subset), so pass B can gate inserts on it.
// ---------------------------------------------------------------------------
__global__ __launch_bounds__(128) void knnA_kernel(const float* __restrict__ flow,
                                                   float* __restrict__ out) {
    const int t = blockIdx.x * 128 + threadIdx.x;
    const float4 qp = g_qS[t];
    const float qx = qp.x, qy = qp.y, qz = qp.z, q2 = qp.w;

    int cx, cy, cz;
    cellCoords(qx, qy, qz, cx, cy, cz);
    const int x0 = max(cx - 1, 0), x1 = min(cx + 1, GD - 1);
    const int y0 = max(cy - 1, 0), y1 = min(cy + 1, GD - 1);
    const int z0 = max(cz - 1, 0), z1 = min(cz + 1, GD - 1);

    float b[KNN];
    int   boid[KNN];
#pragma unroll
    for (int k = 0; k < KNN; ++k) { b[k] = INF_F; boid[k] = 0x7fffffff; }

    for (int zz = z0; zz <= z1; ++zz) {
        for (int yy = y0; yy <= y1; ++yy) {
            int cLo = flatCell(x0, yy, zz);
            int cHi = flatCell(x1, yy, zz);
            int j   = g_startR[cLo];
            int end = g_startR[cHi] + g_cntR[cHi];
#pragma unroll 4
            for (; j < end; ++j) {
                float4 r = g_refS[j];
                float d = fmaf(r.x, qx, fmaf(r.y, qy, fmaf(r.z, qz, r.w)));
                if (d <= b[7]) {                        // hot path: 1 setp
                    int oid = g_refId[j];               // rare path
                    if (d < b[7] || oid < boid[7])
                        insert8(d, oid, b, boid);
                }
            }
        }
    }

    // Exact distance from query to the visited 3x3x3 box boundary.
    float lox = (x0 == 0)      ? -1e30f : (x0 * HCELL - HWORLD);
    float hix = (x1 == GD - 1) ?  1e30f : ((x1 + 1) * HCELL - HWORLD);
    float loy = (y0 == 0)      ? -1e30f : (y0 * HCELL - HWORLD);
    float hiy = (y1 == GD - 1) ?  1e30f : ((y1 + 1) * HCELL - HWORLD);
    float loz = (z0 == 0)      ? -1e30f : (z0 * HCELL - HWORLD);
    float hiz = (z1 == GD - 1) ?  1e30f : ((z1 + 1) * HCELL - HWORLD);

    float m = fminf(qx - lox, hix - qx);
    m = fminf(m, fminf(qy - loy, hiy - qy));
    m = fminf(m, fminf(qz - loz, hiz - qz));

    float d8sq = fmaxf(b[7] + q2, 0.0f);   // inf if list not full
    // STRICT <: a point exactly at distance m could win the origId tie-break.
    bool valid = (b[7] < 1e30f) && (m > 0.0f) && (d8sq < m * m);

    if (!valid) {
        int p = atomicAdd(&g_fbCnt, 1);
        g_fb[p]      = t;
        g_fbSeedD[p] = b[7];      // INF if <8 candidates found -> open gate
        g_fbSeedO[p] = boid[7];
        return;
    }

    // IDW: POWER=2 -> w = 1/(d^2 + eps); no sqrt.
    float wsum = 0.0f, ax = 0.0f, ay = 0.0f, az = 0.0f;
#pragma unroll
    for (int k = 0; k < KNN; ++k) {
        float d2 = fmaxf(b[k] + q2, 0.0f);
        float w  = 1.0f / (d2 + 1e-8f);
        int  id  = boid[k];
        wsum += w;
        ax = fmaf(w, flow[3 * id + 0], ax);
        ay = fmaf(w, flow[3 * id + 1], ay);
        az = fmaf(w, flow[3 * id + 2], az);
    }
    float inv = 1.0f / wsum;
    int qo = g_qId[t];
    out[3 * qo + 0] = ax * inv;
    out[3 * qo + 1] = ay * inv;
    out[3 * qo + 2] = az * inv;
}

// ---------------------------------------------------------------------------
// PASS B: warp-per-query brute force over ALL refs for fallback queries.
// Grid-stride over the fallback list. SEEDED: inserts are gated by the
// pass-A 8th-best (seedD, seedO) key — a proven upper bound on the true d8
// key — so per-lane insert events collapse from ~41 to ~1 and the warp's
// lockstep insert-path cost vanishes. The gated candidate set is a superset
// of the true top-8 (every true member has key <= seed), and each lane keeps
// its 8 smallest, so the merged result is exact.
// ---------------------------------------------------------------------------
#define BWPB     8
#define B_BLOCKS 256    // 2048 warps
__global__ __launch_bounds__(BWPB * 32) void knnB_kernel(const float* __restrict__ flow,
                                                         float* __restrict__ out) {
    const int warpG  = blockIdx.x * BWPB + (threadIdx.x >> 5);
    const int nWarps = gridDim.x * BWPB;
    const int lane   = threadIdx.x & 31;
    const int fbCnt  = g_fbCnt;

    for (int w = warpG; w < fbCnt; w += nWarps) {
        const int   t     = g_fb[w];
        const float seedD = g_fbSeedD[w];
        const int   seedO = g_fbSeedO[w];

        const float4 qp = g_qS[t];
        const float qx = qp.x, qy = qp.y, qz = qp.z, q2 = qp.w;

        float b[KNN];
        int   boid[KNN];
#pragma unroll
        for (int k = 0; k < KNN; ++k) { b[k] = INF_F; boid[k] = 0x7fffffff; }

        // Hot-path threshold: min(current lane worst, seed). Starts at seedD.
        float lim = fminf(b[7], seedD);

        for (int j = lane; j < M_R; j += 32) {   // coalesced across lanes
            float4 r = g_refS[j];
            float d = fmaf(r.x, qx, fmaf(r.y, qy, fmaf(r.z, qz, r.w)));
            if (d <= lim) {                       // hot path: 1 setp
                int oid = g_refId[j];             // rare path below
                bool underSeed = (d < seedD) || (d == seedD && oid <= seedO);
                bool underBest = (d < b[7])  || (d == b[7]  && oid < boid[7]);
                if (underSeed && underBest) {
                    insert8(d, oid, b, boid);
                    lim = fminf(b[7], seedD);
                }
            }
        }

        // Merge: pop the 8 globally smallest by (val, origId); lane r keeps
        // the r-th neighbor so the flow gather runs on lanes 0..7.
        float selD = 0.0f;
        int   selI = 0;
#pragma unroll
        for (int r = 0; r < KNN; ++r) {
            float bv = b[0];
            int   bo = boid[0];
            int   bl = lane;
#pragma unroll
            for (int o = 16; o; o >>= 1) {
                float ov = __shfl_xor_sync(FULLMASK, bv, o);
                int   oo = __shfl_xor_sync(FULLMASK, bo, o);
                int   ol = __shfl_xor_sync(FULLMASK, bl, o);
                if (ov < bv || (ov == bv && oo < bo)) { bv = ov; bo = oo; bl = ol; }
            }
            if (lane == r) { selD = bv; selI = bo; }
            if (lane == bl) {
#pragma unroll
                for (int k = 0; k < KNN - 1; ++k) { b[k] = b[k + 1]; boid[k] = boid[k + 1]; }
                b[KNN - 1] = INF_F; boid[KNN - 1] = 0x7fffffff;
            }
        }

        float ww = 0.0f, fx = 0.0f, fy = 0.0f, fz = 0.0f;
        if (lane < KNN) {
            float d2 = fmaxf(selD + q2, 0.0f);
            ww = 1.0f / (d2 + 1e-8f);
            fx = ww * flow[3 * selI + 0];
            fy = ww * flow[3 * selI + 1];
            fz = ww * flow[3 * selI + 2];
        }
#pragma unroll
        for (int o = 16; o; o >>= 1) {
            ww += __shfl_xor_sync(FULLMASK, ww, o);
            fx += __shfl_xor_sync(FULLMASK, fx, o);
            fy += __shfl_xor_sync(FULLMASK, fy, o);
            fz += __shfl_xor_sync(FULLMASK, fz, o);
        }

        if (lane == 0) {
            float inv = 1.0f / ww;
            int qo = g_qId[t];
            out[3 * qo + 0] = fx * inv;
            out[3 * qo + 1] = fy * inv;
            out[3 * qo + 2] = fz * inv;
        }
    }
}

// ---------------------------------------------------------------------------
extern "C" void kernel_launch(void* const* d_in, const int* in_sizes, int n_in,
                              void* d_out, int out_size) {
    const float* q   = (const float*)d_in[0];  // query_points [N,3]
    const float* r   = (const float*)d_in[1];  // ref_points   [M,3]
    const float* f   = (const float*)d_in[2];  // ref_flow     [M,3]
    float*       out = (float*)d_out;          // [N,3]

    zero_kernel<<<(2 * CELLS + 255) / 256, 256>>>();
    count_all<<<(M_R + N_Q + 255) / 256, 256>>>(r, q);
    scan1_kernel<<<2 * SCAN_BLKS, SCAN_ELEMS>>>();
    scan2_kernel<<<1, 32>>>();
    scan3_kernel<<<2 * SCAN_BLKS, SCAN_ELEMS>>>();
    scatter_all<<<(M_R + N_Q + 255) / 256, 256>>>(r, q);
    knnA_kernel<<<N_Q / 128, 128>>>(f, out);
    knnB_kernel<<<B_BLOCKS, BWPB * 32>>>(f, out);
}